// round 7
// baseline (speedup 1.0000x reference)
#include <cuda_runtime.h>
#include <math.h>

#define NB 2
#define RR 360
#define RRH 180
#define NN 100
#define SS 200
#define KXN 101
#define NPIX (NN*NN)
#define NLIGH (NB*RRH*2)          // 720 forward-transformed ligand images
#define NIMGH (NLIGH + NB*2)      // +4 receptor images = 724
#define GPITCH 102

// ---------------- scratch (device globals; no allocation allowed) ----------
__device__ float  d_h1[4][9][NPIX];
__device__ float  d_feat[4][2][NPIX];            // 0..1 receptor b, 2..3 ligand b
__device__ float2 d_G[NIMGH][NN][GPITCH];        // row DFT: [img][y][kx]
__device__ float2 d_F[NIMGH][KXN][SS];           // fwd spectrum: [img][kx][ky]
__device__ float2 d_H[NB*RR][KXN][SS];           // after inv-ky: [imgH][kx][y]
__device__ unsigned int d_best[NB];
__device__ float  d_pos[NB];

// e^{i pi j/4}: cos, sin tables (exact-to-eps reseed points)
__device__ __constant__ float C8[8] = {1.f, 0.70710678118654752f, 0.f, -0.70710678118654752f,
                                       -1.f, -0.70710678118654752f, 0.f, 0.70710678118654752f};
__device__ __constant__ float S8[8] = {0.f, 0.70710678118654752f, 1.f, 0.70710678118654752f,
                                       0.f, -0.70710678118654752f, -1.f, -0.70710678118654752f};

__device__ __forceinline__ unsigned fenc(float f) {
    unsigned u = __float_as_uint(f);
    return (u & 0x80000000u) ? ~u : (u | 0x80000000u);
}
__device__ __forceinline__ float fdec(unsigned e) {
    unsigned u = (e & 0x80000000u) ? (e & 0x7FFFFFFFu) : ~e;
    return __uint_as_float(u);
}

__global__ void k_init() {
    int t = threadIdx.x;
    if (t < NB) { d_best[t] = 0u; d_pos[t] = 0.0f; }
}

// ---------------- conv1 + norm_relu (FIELDS1) -------------------------------
__global__ void k_conv1(const float* __restrict__ rec, const float* __restrict__ lig,
                        const float* __restrict__ w1) {
    int img = blockIdx.y;
    int p = blockIdx.x * blockDim.x + threadIdx.x;
    if (p >= NPIX) return;
    int y = p / NN, x = p % NN;
    const float* src = (img < NB) ? (rec + img * NPIX) : (lig + (img - NB) * NPIX);
    float acc[9];
#pragma unroll
    for (int o = 0; o < 9; o++) acc[o] = 0.0f;
#pragma unroll
    for (int ky = 0; ky < 5; ky++) {
        int iy = y + ky - 2;
        if ((unsigned)iy >= NN) continue;
#pragma unroll
        for (int kx = 0; kx < 5; kx++) {
            int ix = x + kx - 2;
            if ((unsigned)ix >= NN) continue;
            float v = __ldg(src + iy * NN + ix);
#pragma unroll
            for (int o = 0; o < 9; o++)
                acc[o] = fmaf(v, __ldg(w1 + o * 25 + ky * 5 + kx), acc[o]);
        }
    }
    {
        float a = acc[0];
        float n = sqrtf(a * a + 1e-12f);
        d_h1[img][0][p] = a * (n / (n + 1e-12f));
    }
#pragma unroll
    for (int g = 0; g < 4; g++) {
        int s = 1 + 2 * g;
        float a = acc[s], b = acc[s + 1];
        float n = sqrtf(a * a + b * b + 1e-12f);
        float sc = n / (n + 1e-12f);
        d_h1[img][s][p] = a * sc;
        d_h1[img][s + 1][p] = b * sc;
    }
}

// ---------------- conv2 + norm_relu (FIELDS2) + features --------------------
__global__ void k_conv2(const float* __restrict__ w2) {
    int img = blockIdx.y;
    int p = blockIdx.x * blockDim.x + threadIdx.x;
    if (p >= NPIX) return;
    int y = p / NN, x = p % NN;
    float acc[3] = {0.f, 0.f, 0.f};
    for (int ci = 0; ci < 9; ci++) {
        const float* hp = d_h1[img][ci];
#pragma unroll
        for (int ky = 0; ky < 5; ky++) {
            int iy = y + ky - 2;
            if ((unsigned)iy >= NN) continue;
#pragma unroll
            for (int kx = 0; kx < 5; kx++) {
                int ix = x + kx - 2;
                if ((unsigned)ix >= NN) continue;
                float v = hp[iy * NN + ix];
#pragma unroll
                for (int o = 0; o < 3; o++)
                    acc[o] = fmaf(v, __ldg(w2 + ((o * 9 + ci) * 5 + ky) * 5 + kx), acc[o]);
            }
        }
    }
    float o0, o1, o2;
    {
        float a = acc[0];
        float n = sqrtf(a * a + 1e-12f);
        o0 = a * (n / (n + 1e-12f));
    }
    {
        float a = acc[1], b = acc[2];
        float n = sqrtf(a * a + b * b + 1e-12f);
        float sc = n / (n + 1e-12f);
        o1 = a * sc; o2 = b * sc;
    }
    d_feat[img][0][p] = fabsf(o0);
    d_feat[img][1][p] = sqrtf(o1 * o1 + o2 * o2 + 1e-12f);
}

__device__ __forceinline__ float samp(const float* __restrict__ im, float yf, float xf) {
    if (yf < 0.f || yf >= 100.f || xf < 0.f || xf >= 100.f) return 0.f;
    int yc = (int)yf, xc = (int)xf;
    return im[yc * NN + xc];
}

// ---------------- rotate (fused) + row DFT ----------------------------------
// Only rotations r = 0..179 computed; r+180 derived later via phase*conj.
__global__ void __launch_bounds__(256) k_rot_rowdft() {
    __shared__ __align__(16) float rotT[NN * 104];   // [x][y], pitch 104
    int bid = blockIdx.x;
    int tid = threadIdx.x;
    const float* src;
    bool ident;
    float ct = 1.f, st = 0.f;
    if (bid < NLIGH) {
        int c = bid & 1;
        int r = (bid >> 1) % RRH;
        int b = bid / (2 * RRH);
        src = d_feat[NB + b][c];
        double th = -3.14159265358979323846 + (double)r * (6.283185307179586477 / 360.0);
        ct = (float)cos(th); st = (float)sin(th);
        ident = false;
    } else {
        int i = bid - NLIGH;
        src = d_feat[i >> 1][i & 1];
        ident = true;
    }
    for (int p = tid; p < NPIX; p += blockDim.x) {
        int i = p / NN, j = p % NN;
        float val;
        if (ident) {
            val = src[p];
        } else {
            float xs = (float)j - 49.5f, ys = (float)i - 49.5f;
            float xq = ct * xs + st * ys + 49.5f;
            float yq = -st * xs + ct * ys + 49.5f;
            float x0f = floorf(xq), y0f = floorf(yq);
            float wx = xq - x0f, wy = yq - y0f;
            val = samp(src, y0f, x0f) * (1.f - wy) * (1.f - wx)
                + samp(src, y0f, x0f + 1.f) * (1.f - wy) * wx
                + samp(src, y0f + 1.f, x0f) * wy * (1.f - wx)
                + samp(src, y0f + 1.f, x0f + 1.f) * wy * wx;
        }
        rotT[j * 104 + i] = val;   // transposed store
    }
    __syncthreads();
    for (int task = tid; task < 5 * KXN; task += 256) {
        int kx = task % KXN;
        int y0 = (task / KXN) * 20;
        float sif, srf;
        sincosf(-3.14159265358979f * (float)kx * 0.01f, &sif, &srf);  // step e^{-i pi kx/100}
        float wr = 1.f, wi = 0.f;
        float aR[20], aI[20];
#pragma unroll
        for (int i = 0; i < 20; i++) { aR[i] = 0.f; aI[i] = 0.f; }
        for (int x = 0; x < NN; x++) {
            if ((x & 24) && (x % 25 == 0)) {      // x = 25, 50, 75: exact reseed
                int j = (kx * (x / 25)) & 7;      // phase = -pi*j/4
                wr = C8[j]; wi = -S8[j];
            }
            const float4* rp = reinterpret_cast<const float4*>(&rotT[x * 104 + y0]);
#pragma unroll
            for (int q = 0; q < 5; q++) {
                float4 v = rp[q];
                aR[q*4+0] = fmaf(v.x, wr, aR[q*4+0]); aI[q*4+0] = fmaf(v.x, wi, aI[q*4+0]);
                aR[q*4+1] = fmaf(v.y, wr, aR[q*4+1]); aI[q*4+1] = fmaf(v.y, wi, aI[q*4+1]);
                aR[q*4+2] = fmaf(v.z, wr, aR[q*4+2]); aI[q*4+2] = fmaf(v.z, wi, aI[q*4+2]);
                aR[q*4+3] = fmaf(v.w, wr, aR[q*4+3]); aI[q*4+3] = fmaf(v.w, wi, aI[q*4+3]);
            }
            float nr = fmaf(wr, srf, -wi * sif);
            float ni = fmaf(wr, sif, wi * srf);
            wr = nr; wi = ni;
        }
#pragma unroll
        for (int i = 0; i < 20; i++)
            d_G[bid][y0 + i][kx] = make_float2(aR[i], aI[i]);
    }
}

// ---------------- column DFT with radix-2 input split -----------------------
__global__ void __launch_bounds__(256) k_coldft() {
    __shared__ __align__(16) float2 GT[NN][56];   // [y][kx-local]
    int img = blockIdx.x >> 1;
    int half = blockIdx.x & 1;
    int kxg0 = half * 52;
    int width = half ? 49 : 52;
    int tid = threadIdx.x;
    for (int t = tid; t < NN * 56; t += 256) {
        int y = t / 56, kxl = t % 56;
        GT[y][kxl] = (kxl < width) ? d_G[img][y][kxg0 + kxl] : make_float2(0.f, 0.f);
    }
    __syncthreads();
    for (int task = tid; task < 700; task += 256) {
        int u = task % 100;
        int kxl0 = (task / 100) * 8;
        int uw = (u > 50) ? u - 100 : u;
        float sif, srf;
        sincosf(-6.28318530717959f * (float)uw * 0.01f, &sif, &srf);
        float wr = 1.f, wi = 0.f;
        float Ar[8], Ai[8], Br[8], Bi[8];
#pragma unroll
        for (int j = 0; j < 8; j++) { Ar[j]=Ai[j]=Br[j]=Bi[j]=0.f; }
        for (int v = 0; v < 50; v++) {
            if (v == 25) {                         // phase = -pi*u/2 exact
                int j = (2 * u) & 7;
                wr = C8[j]; wi = -S8[j];
            }
            const float4* pe = reinterpret_cast<const float4*>(&GT[2*v][kxl0]);
            const float4* po = reinterpret_cast<const float4*>(&GT[2*v+1][kxl0]);
#pragma unroll
            for (int q = 0; q < 4; q++) {
                float4 e = pe[q];
                Ar[2*q]   = fmaf(e.x, wr, Ar[2*q]);   Ar[2*q]   = fmaf(-e.y, wi, Ar[2*q]);
                Ai[2*q]   = fmaf(e.x, wi, Ai[2*q]);   Ai[2*q]   = fmaf( e.y, wr, Ai[2*q]);
                Ar[2*q+1] = fmaf(e.z, wr, Ar[2*q+1]); Ar[2*q+1] = fmaf(-e.w, wi, Ar[2*q+1]);
                Ai[2*q+1] = fmaf(e.z, wi, Ai[2*q+1]); Ai[2*q+1] = fmaf( e.w, wr, Ai[2*q+1]);
                float4 o = po[q];
                Br[2*q]   = fmaf(o.x, wr, Br[2*q]);   Br[2*q]   = fmaf(-o.y, wi, Br[2*q]);
                Bi[2*q]   = fmaf(o.x, wi, Bi[2*q]);   Bi[2*q]   = fmaf( o.y, wr, Bi[2*q]);
                Br[2*q+1] = fmaf(o.z, wr, Br[2*q+1]); Br[2*q+1] = fmaf(-o.w, wi, Br[2*q+1]);
                Bi[2*q+1] = fmaf(o.z, wi, Bi[2*q+1]); Bi[2*q+1] = fmaf( o.w, wr, Bi[2*q+1]);
            }
            float nr = fmaf(wr, srf, -wi * sif);
            float ni = fmaf(wr, sif, wi * srf);
            wr = nr; wi = ni;
        }
        float tr, ti;
        sincosf(-3.14159265358979f * (float)u * 0.01f, &ti, &tr);
#pragma unroll
        for (int j = 0; j < 8; j++) {
            int kxl = kxl0 + j;
            if (kxl >= width) continue;
            int kx = kxg0 + kxl;
            float tbr = tr * Br[j] - ti * Bi[j];
            float tbi = tr * Bi[j] + ti * Br[j];
            d_F[img][kx][u]       = make_float2(Ar[j] + tbr, Ai[j] + tbi);
            d_F[img][kx][u + 100] = make_float2(Ar[j] - tbr, Ai[j] - tbi);
        }
    }
}

// ---------------- combine spectra + inverse ky (radix-2 output split) -------
// For r>=180: lig spectrum synthesized as ph(kx+ky)*conj(F[r-180]),
// ph(s) = e^{-i pi 99 s/100} = (-1)^s (cos(pi s/100) + i sin(pi s/100)).
__global__ void __launch_bounds__(320) k_combine_invy(const float* __restrict__ wb,
        const float* __restrict__ wc1, const float* __restrict__ wc2,
        const float* __restrict__ wk) {
    __shared__ __align__(16) float2 sfs[SS][24];
    int chunk = blockIdx.x % 5;
    int imgH = blockIdx.x / 5;
    int b = imgH / RR;
    int r = imgH % RR;
    bool flip = (r >= RRH);
    int rb180 = flip ? r - RRH : r;
    int kxg0 = chunk * 24;
    int width = (KXN - kxg0 < 24) ? (KXN - kxg0) : 24;
    int tid = threadIdx.x;
    float w0 = *wb, w1v = *wc1, w2v = *wc2, w3 = *wk;
    int imgL0 = (b * RRH + rb180) * 2, imgL1 = imgL0 + 1;
    int imgR0 = NLIGH + b * 2, imgR1 = imgR0 + 1;
    for (int e = tid; e < SS * 24; e += 320) {
        int ky = e % SS, kxl = e / SS;
        float2 v = make_float2(0.f, 0.f);
        if (kxl < width) {
            int kx = kxg0 + kxl;
            float2 lb = d_F[imgL0][kx][ky];
            float2 lB = d_F[imgL1][kx][ky];
            if (flip) {
                int s = kx + ky;
                float pr, pi_;
                sincosf(3.14159265358979f * 0.01f * (float)s, &pi_, &pr);
                if (s & 1) { pr = -pr; pi_ = -pi_; }
                float t;
                t    = pr * lb.x + pi_ * lb.y;      // Re(ph*conj(lb))
                lb.y = pi_ * lb.x - pr * lb.y;      // Im(ph*conj(lb))
                lb.x = t;
                t    = pr * lB.x + pi_ * lB.y;
                lB.y = pi_ * lB.x - pr * lB.y;
                lB.x = t;
            }
            float2 rb = d_F[imgR0][kx][ky];
            float2 rB = d_F[imgR1][kx][ky];
            float ur = w0 * lb.x + w1v * lB.x, ui = w0 * lb.y + w1v * lB.y;
            float vr = w2v * lb.x - w3 * lB.x, vi = w2v * lb.y - w3 * lB.y;
            v.x = rb.x * ur + rb.y * ui + rB.x * vr + rB.y * vi;
            v.y = rb.x * ui - rb.y * ur + rB.x * vi - rB.y * vr;
        }
        sfs[ky][kxl] = v;
    }
    __syncthreads();
    for (int task = tid; task < 300; task += 320) {
        int u = task % 100;
        int kxl0 = (task / 100) * 8;
        int uw = (u > 50) ? u - 100 : u;
        float sif, srf;
        sincosf(6.28318530717959f * (float)uw * 0.01f, &sif, &srf);
        float wr = 1.f, wi = 0.f;
        float Pr[8], Pi[8], Qr[8], Qi[8];
#pragma unroll
        for (int j = 0; j < 8; j++) { Pr[j]=Pi[j]=Qr[j]=Qi[j]=0.f; }
        for (int m = 0; m < 100; m++) {
            if ((m & 24) && (m % 25 == 0)) {       // m = 25,50,75
                int j = (2 * u * (m / 25)) & 7;
                wr = C8[j]; wi = S8[j];
            }
            const float4* pe = reinterpret_cast<const float4*>(&sfs[2*m][kxl0]);
            const float4* po = reinterpret_cast<const float4*>(&sfs[2*m+1][kxl0]);
#pragma unroll
            for (int q = 0; q < 4; q++) {
                float4 e = pe[q];
                Pr[2*q]   = fmaf(e.x, wr, Pr[2*q]);   Pr[2*q]   = fmaf(-e.y, wi, Pr[2*q]);
                Pi[2*q]   = fmaf(e.x, wi, Pi[2*q]);   Pi[2*q]   = fmaf( e.y, wr, Pi[2*q]);
                Pr[2*q+1] = fmaf(e.z, wr, Pr[2*q+1]); Pr[2*q+1] = fmaf(-e.w, wi, Pr[2*q+1]);
                Pi[2*q+1] = fmaf(e.z, wi, Pi[2*q+1]); Pi[2*q+1] = fmaf( e.w, wr, Pi[2*q+1]);
                float4 o = po[q];
                Qr[2*q]   = fmaf(o.x, wr, Qr[2*q]);   Qr[2*q]   = fmaf(-o.y, wi, Qr[2*q]);
                Qi[2*q]   = fmaf(o.x, wi, Qi[2*q]);   Qi[2*q]   = fmaf( o.y, wr, Qi[2*q]);
                Qr[2*q+1] = fmaf(o.z, wr, Qr[2*q+1]); Qr[2*q+1] = fmaf(-o.w, wi, Qr[2*q+1]);
                Qi[2*q+1] = fmaf(o.z, wi, Qi[2*q+1]); Qi[2*q+1] = fmaf( o.w, wr, Qi[2*q+1]);
            }
            float nr = fmaf(wr, srf, -wi * sif);
            float ni = fmaf(wr, sif, wi * srf);
            wr = nr; wi = ni;
        }
        float tr, ti;
        sincosf(3.14159265358979f * (float)u * 0.01f, &ti, &tr);
#pragma unroll
        for (int j = 0; j < 8; j++) {
            int kxl = kxl0 + j;
            if (kxl >= width) continue;
            int kx = kxg0 + kxl;
            float tqr = tr * Qr[j] - ti * Qi[j];
            float tqi = tr * Qi[j] + ti * Qr[j];
            d_H[imgH][kx][u]       = make_float2(Pr[j] + tqr, Pi[j] + tqi);
            d_H[imgH][kx][u + 100] = make_float2(Pr[j] - tqr, Pi[j] - tqi);
        }
    }
}

// ---------------- inverse kx (real, radix-2 output split) + reduce ----------
__global__ void __launch_bounds__(256) k_invx_reduce(const int* __restrict__ gtr,
                                                     const int* __restrict__ gtt) {
    __shared__ __align__(16) float2 HT[KXN][20];
    __shared__ float red[256];
    int yc = blockIdx.x % 10;
    int imgH = blockIdx.x / 10;
    int b = imgH / RR, r = imgH % RR;
    int ybase = yc * 20;
    int tid = threadIdx.x;
    for (int e = tid; e < KXN * 20; e += 256) {
        int kx = e / 20, yl = e % 20;
        HT[kx][yl] = d_H[imgH][kx][ybase + yl];
    }
    __syncthreads();
    int gr = gtr[b], t0 = gtt[2 * b], t1 = gtt[2 * b + 1];
    const float inv = 1.0f / 40000.0f;
    float lmax = -3.4e38f;
    for (int task = tid; task < 200; task += 256) {
        int u = task % 100;
        int y0 = (task / 100) * 10;
        int uw = (u > 50) ? u - 100 : u;
        float sif, srf;
        sincosf(6.28318530717959f * (float)uw * 0.01f, &sif, &srf);
        float wr = 1.f, wi = 0.f;
        float E[10], Cr[10], Ci[10];
        float sgn = (u & 1) ? -1.f : 1.f;
#pragma unroll
        for (int i = 0; i < 10; i++) {
            E[i]  = HT[0][y0 + i].x + sgn * HT[100][y0 + i].x;
            Cr[i] = HT[1][y0 + i].x;
            Ci[i] = HT[1][y0 + i].y;
        }
        for (int m = 1; m < 50; m++) {
            float nr = fmaf(wr, srf, -wi * sif);
            float ni = fmaf(wr, sif, wi * srf);
            wr = nr; wi = ni;
            if (m == 25) {
                int j = (2 * u) & 7;
                wr = C8[j]; wi = S8[j];
            }
            float w2r = 2.f * wr, w2i = 2.f * wi;
            const float4* pe = reinterpret_cast<const float4*>(&HT[2*m][y0]);
            const float4* po = reinterpret_cast<const float4*>(&HT[2*m+1][y0]);
#pragma unroll
            for (int q = 0; q < 5; q++) {
                float4 e = pe[q];
                E[2*q]   = fmaf(e.x, w2r, E[2*q]);   E[2*q]   = fmaf(-e.y, w2i, E[2*q]);
                E[2*q+1] = fmaf(e.z, w2r, E[2*q+1]); E[2*q+1] = fmaf(-e.w, w2i, E[2*q+1]);
                float4 o = po[q];
                Cr[2*q]   = fmaf(o.x, wr, Cr[2*q]);   Cr[2*q]   = fmaf(-o.y, wi, Cr[2*q]);
                Ci[2*q]   = fmaf(o.x, wi, Ci[2*q]);   Ci[2*q]   = fmaf( o.y, wr, Ci[2*q]);
                Cr[2*q+1] = fmaf(o.z, wr, Cr[2*q+1]); Cr[2*q+1] = fmaf(-o.w, wi, Cr[2*q+1]);
                Ci[2*q+1] = fmaf(o.z, wi, Ci[2*q+1]); Ci[2*q+1] = fmaf( o.w, wr, Ci[2*q+1]);
            }
        }
        float tr, ti;
        sincosf(3.14159265358979f * (float)u * 0.01f, &ti, &tr);
#pragma unroll
        for (int i = 0; i < 10; i++) {
            float oc = 2.f * (Cr[i] * tr - Ci[i] * ti);
            float s0 = (E[i] + oc) * inv;
            float s1 = (E[i] - oc) * inv;
            lmax = fmaxf(lmax, fmaxf(s0, s1));
            int y = ybase + y0 + i;
            if (r == gr && y == t0) {
                if (u == t1) d_pos[b] = s0;
                if (u + 100 == t1) d_pos[b] = s1;
            }
        }
    }
    red[tid] = lmax;
    __syncthreads();
    for (int s2 = 128; s2 > 0; s2 >>= 1) {
        if (tid < s2) red[tid] = fmaxf(red[tid], red[tid + s2]);
        __syncthreads();
    }
    if (tid == 0) atomicMax(&d_best[b], fenc(red[0]));
}

__global__ void k_final(float* __restrict__ out) {
    if (threadIdx.x == 0) {
        float lp = 0.f, ln = 0.f;
        for (int b = 0; b < NB; b++) {
            float p = d_pos[b];
            lp += p + p * p;
            float m = fdec(d_best[b]);
            ln += -m + m * m;
        }
        out[0] = lp / (float)NB;
        out[1] = ln / (float)NB;
    }
}

extern "C" void kernel_launch(void* const* d_in, const int* in_sizes, int n_in,
                              void* d_out, int out_size) {
    const float* rec = (const float*)d_in[0];
    const float* lig = (const float*)d_in[1];
    const float* w1 = (const float*)d_in[2];
    const float* w2 = (const float*)d_in[3];
    const float* wb = (const float*)d_in[4];
    const float* wc1 = (const float*)d_in[5];
    const float* wc2 = (const float*)d_in[6];
    const float* wk = (const float*)d_in[7];
    const int* gtr = (const int*)d_in[8];
    const int* gtt = (const int*)d_in[9];
    float* out = (float*)d_out;

    k_init<<<1, 32>>>();
    dim3 gconv((NPIX + 255) / 256, 4);
    k_conv1<<<gconv, 256>>>(rec, lig, w1);
    k_conv2<<<gconv, 256>>>(w2);
    k_rot_rowdft<<<NIMGH, 256>>>();
    k_coldft<<<NIMGH * 2, 256>>>();
    k_combine_invy<<<NB * RR * 5, 320>>>(wb, wc1, wc2, wk);
    k_invx_reduce<<<NB * RR * 10, 256>>>(gtr, gtt);
    k_final<<<1, 32>>>(out);
}

// round 9
// speedup vs baseline: 1.6431x; 1.6431x over previous
#include <cuda_runtime.h>
#include <math.h>

#define NB 2
#define RR 360
#define RRH 180
#define NN 100
#define SS 200
#define KXN 101
#define NPIX (NN*NN)
#define NLIGH (NB*RRH*2)          // 720 forward-transformed ligand images
#define NIMGH (NLIGH + NB*2)      // +4 receptor images = 724
#define GPITCH 102

// ---------------- scratch (device globals; no allocation allowed) ----------
__device__ float  d_h1[4][9][NPIX];
__device__ float  d_feat[4][2][NPIX];            // 0..1 receptor b, 2..3 ligand b
__device__ float2 d_G[NIMGH][NN][GPITCH];        // row DFT: [img][y][kx]
__device__ float2 d_F[NIMGH][KXN][SS];           // fwd spectrum: [img][kx][ky]
__device__ float2 d_H[NB*RR][KXN][SS];           // after inv-ky: [imgH][kx][y]
__device__ unsigned int d_best[NB];
__device__ float  d_pos[NB];

// e^{i pi j/4}: cos, sin tables (exact-to-eps reseed points)
__device__ __constant__ float C8[8] = {1.f, 0.70710678118654752f, 0.f, -0.70710678118654752f,
                                       -1.f, -0.70710678118654752f, 0.f, 0.70710678118654752f};
__device__ __constant__ float S8[8] = {0.f, 0.70710678118654752f, 1.f, 0.70710678118654752f,
                                       0.f, -0.70710678118654752f, -1.f, -0.70710678118654752f};

__device__ __forceinline__ unsigned fenc(float f) {
    unsigned u = __float_as_uint(f);
    return (u & 0x80000000u) ? ~u : (u | 0x80000000u);
}
__device__ __forceinline__ float fdec(unsigned e) {
    unsigned u = (e & 0x80000000u) ? (e & 0x7FFFFFFFu) : ~e;
    return __uint_as_float(u);
}

__global__ void k_init() {
    int t = threadIdx.x;
    if (t < NB) { d_best[t] = 0u; d_pos[t] = 0.0f; }
}

// ---------------- conv1 + norm_relu (FIELDS1) -------------------------------
__global__ void k_conv1(const float* __restrict__ rec, const float* __restrict__ lig,
                        const float* __restrict__ w1) {
    int img = blockIdx.y;
    int p = blockIdx.x * blockDim.x + threadIdx.x;
    if (p >= NPIX) return;
    int y = p / NN, x = p % NN;
    const float* src = (img < NB) ? (rec + img * NPIX) : (lig + (img - NB) * NPIX);
    float acc[9];
#pragma unroll
    for (int o = 0; o < 9; o++) acc[o] = 0.0f;
#pragma unroll
    for (int ky = 0; ky < 5; ky++) {
        int iy = y + ky - 2;
        if ((unsigned)iy >= NN) continue;
#pragma unroll
        for (int kx = 0; kx < 5; kx++) {
            int ix = x + kx - 2;
            if ((unsigned)ix >= NN) continue;
            float v = __ldg(src + iy * NN + ix);
#pragma unroll
            for (int o = 0; o < 9; o++)
                acc[o] = fmaf(v, __ldg(w1 + o * 25 + ky * 5 + kx), acc[o]);
        }
    }
    {
        float a = acc[0];
        float n = sqrtf(a * a + 1e-12f);
        d_h1[img][0][p] = a * (n / (n + 1e-12f));
    }
#pragma unroll
    for (int g = 0; g < 4; g++) {
        int s = 1 + 2 * g;
        float a = acc[s], b = acc[s + 1];
        float n = sqrtf(a * a + b * b + 1e-12f);
        float sc = n / (n + 1e-12f);
        d_h1[img][s][p] = a * sc;
        d_h1[img][s + 1][p] = b * sc;
    }
}

// ---------------- conv2 + norm_relu (FIELDS2) + features --------------------
__global__ void k_conv2(const float* __restrict__ w2) {
    int img = blockIdx.y;
    int p = blockIdx.x * blockDim.x + threadIdx.x;
    if (p >= NPIX) return;
    int y = p / NN, x = p % NN;
    float acc[3] = {0.f, 0.f, 0.f};
    for (int ci = 0; ci < 9; ci++) {
        const float* hp = d_h1[img][ci];
#pragma unroll
        for (int ky = 0; ky < 5; ky++) {
            int iy = y + ky - 2;
            if ((unsigned)iy >= NN) continue;
#pragma unroll
            for (int kx = 0; kx < 5; kx++) {
                int ix = x + kx - 2;
                if ((unsigned)ix >= NN) continue;
                float v = hp[iy * NN + ix];
#pragma unroll
                for (int o = 0; o < 3; o++)
                    acc[o] = fmaf(v, __ldg(w2 + ((o * 9 + ci) * 5 + ky) * 5 + kx), acc[o]);
            }
        }
    }
    float o0, o1, o2;
    {
        float a = acc[0];
        float n = sqrtf(a * a + 1e-12f);
        o0 = a * (n / (n + 1e-12f));
    }
    {
        float a = acc[1], b = acc[2];
        float n = sqrtf(a * a + b * b + 1e-12f);
        float sc = n / (n + 1e-12f);
        o1 = a * sc; o2 = b * sc;
    }
    d_feat[img][0][p] = fabsf(o0);
    d_feat[img][1][p] = sqrtf(o1 * o1 + o2 * o2 + 1e-12f);
}

__device__ __forceinline__ float samp(const float* __restrict__ im, float yf, float xf) {
    if (yf < 0.f || yf >= 100.f || xf < 0.f || xf >= 100.f) return 0.f;
    int yc = (int)yf, xc = (int)xf;
    return im[yc * NN + xc];
}

// ---------------- rotate (fused) + row DFT ----------------------------------
// Only rotations r = 0..179 computed; r+180 derived later via phase*conj.
__global__ void __launch_bounds__(256) k_rot_rowdft() {
    __shared__ __align__(16) float rotT[NN * 104];   // [x][y], pitch 104
    int bid = blockIdx.x;
    int tid = threadIdx.x;
    const float* src;
    bool ident;
    float ct = 1.f, st = 0.f;
    if (bid < NLIGH) {
        int c = bid & 1;
        int r = (bid >> 1) % RRH;
        int b = bid / (2 * RRH);
        src = d_feat[NB + b][c];
        double th = -3.14159265358979323846 + (double)r * (6.283185307179586477 / 360.0);
        ct = (float)cos(th); st = (float)sin(th);
        ident = false;
    } else {
        int i = bid - NLIGH;
        src = d_feat[i >> 1][i & 1];
        ident = true;
    }
    for (int p = tid; p < NPIX; p += blockDim.x) {
        int i = p / NN, j = p % NN;
        float val;
        if (ident) {
            val = src[p];
        } else {
            float xs = (float)j - 49.5f, ys = (float)i - 49.5f;
            float xq = ct * xs + st * ys + 49.5f;
            float yq = -st * xs + ct * ys + 49.5f;
            float x0f = floorf(xq), y0f = floorf(yq);
            float wx = xq - x0f, wy = yq - y0f;
            val = samp(src, y0f, x0f) * (1.f - wy) * (1.f - wx)
                + samp(src, y0f, x0f + 1.f) * (1.f - wy) * wx
                + samp(src, y0f + 1.f, x0f) * wy * (1.f - wx)
                + samp(src, y0f + 1.f, x0f + 1.f) * wy * wx;
        }
        rotT[j * 104 + i] = val;   // transposed store
    }
    __syncthreads();
    for (int task = tid; task < 5 * KXN; task += 256) {
        int kx = task % KXN;
        int y0 = (task / KXN) * 20;
        float sif, srf;
        sincosf(-3.14159265358979f * (float)kx * 0.01f, &sif, &srf);  // step e^{-i pi kx/100}
        float wr = 1.f, wi = 0.f;
        float aR[20], aI[20];
#pragma unroll
        for (int i = 0; i < 20; i++) { aR[i] = 0.f; aI[i] = 0.f; }
        for (int x = 0; x < NN; x++) {
            if ((x & 24) && (x % 25 == 0)) {      // x = 25, 50, 75: exact reseed
                int j = (kx * (x / 25)) & 7;      // phase = -pi*j/4
                wr = C8[j]; wi = -S8[j];
            }
            const float4* rp = reinterpret_cast<const float4*>(&rotT[x * 104 + y0]);
#pragma unroll
            for (int q = 0; q < 5; q++) {
                float4 v = rp[q];
                aR[q*4+0] = fmaf(v.x, wr, aR[q*4+0]); aI[q*4+0] = fmaf(v.x, wi, aI[q*4+0]);
                aR[q*4+1] = fmaf(v.y, wr, aR[q*4+1]); aI[q*4+1] = fmaf(v.y, wi, aI[q*4+1]);
                aR[q*4+2] = fmaf(v.z, wr, aR[q*4+2]); aI[q*4+2] = fmaf(v.z, wi, aI[q*4+2]);
                aR[q*4+3] = fmaf(v.w, wr, aR[q*4+3]); aI[q*4+3] = fmaf(v.w, wi, aI[q*4+3]);
            }
            float nr = fmaf(wr, srf, -wi * sif);
            float ni = fmaf(wr, sif, wi * srf);
            wr = nr; wi = ni;
        }
#pragma unroll
        for (int i = 0; i < 20; i++)
            d_G[bid][y0 + i][kx] = make_float2(aR[i], aI[i]);
    }
}

// ---------------- column DFT with radix-2 input split -----------------------
__global__ void __launch_bounds__(256) k_coldft() {
    __shared__ __align__(16) float2 GT[NN][56];   // [y][kx-local]
    int img = blockIdx.x >> 1;
    int half = blockIdx.x & 1;
    int kxg0 = half * 52;
    int width = half ? 49 : 52;
    int tid = threadIdx.x;
    for (int t = tid; t < NN * 56; t += 256) {
        int y = t / 56, kxl = t % 56;
        GT[y][kxl] = (kxl < width) ? d_G[img][y][kxg0 + kxl] : make_float2(0.f, 0.f);
    }
    __syncthreads();
    for (int task = tid; task < 700; task += 256) {
        int u = task % 100;
        int kxl0 = (task / 100) * 8;
        int uw = (u > 50) ? u - 100 : u;
        float sif, srf;
        sincosf(-6.28318530717959f * (float)uw * 0.01f, &sif, &srf);
        float wr = 1.f, wi = 0.f;
        float Ar[8], Ai[8], Br[8], Bi[8];
#pragma unroll
        for (int j = 0; j < 8; j++) { Ar[j]=Ai[j]=Br[j]=Bi[j]=0.f; }
        for (int v = 0; v < 50; v++) {
            if (v == 25) {                         // phase = -pi*u/2 exact
                int j = (2 * u) & 7;
                wr = C8[j]; wi = -S8[j];
            }
            const float4* pe = reinterpret_cast<const float4*>(&GT[2*v][kxl0]);
            const float4* po = reinterpret_cast<const float4*>(&GT[2*v+1][kxl0]);
#pragma unroll
            for (int q = 0; q < 4; q++) {
                float4 e = pe[q];
                Ar[2*q]   = fmaf(e.x, wr, Ar[2*q]);   Ar[2*q]   = fmaf(-e.y, wi, Ar[2*q]);
                Ai[2*q]   = fmaf(e.x, wi, Ai[2*q]);   Ai[2*q]   = fmaf( e.y, wr, Ai[2*q]);
                Ar[2*q+1] = fmaf(e.z, wr, Ar[2*q+1]); Ar[2*q+1] = fmaf(-e.w, wi, Ar[2*q+1]);
                Ai[2*q+1] = fmaf(e.z, wi, Ai[2*q+1]); Ai[2*q+1] = fmaf( e.w, wr, Ai[2*q+1]);
                float4 o = po[q];
                Br[2*q]   = fmaf(o.x, wr, Br[2*q]);   Br[2*q]   = fmaf(-o.y, wi, Br[2*q]);
                Bi[2*q]   = fmaf(o.x, wi, Bi[2*q]);   Bi[2*q]   = fmaf( o.y, wr, Bi[2*q]);
                Br[2*q+1] = fmaf(o.z, wr, Br[2*q+1]); Br[2*q+1] = fmaf(-o.w, wi, Br[2*q+1]);
                Bi[2*q+1] = fmaf(o.z, wi, Bi[2*q+1]); Bi[2*q+1] = fmaf( o.w, wr, Bi[2*q+1]);  // FIX: wr (was wi typo)
            }
            float nr = fmaf(wr, srf, -wi * sif);
            float ni = fmaf(wr, sif, wi * srf);
            wr = nr; wi = ni;
        }
        float tr, ti;
        sincosf(-3.14159265358979f * (float)u * 0.01f, &ti, &tr);
#pragma unroll
        for (int j = 0; j < 8; j++) {
            int kxl = kxl0 + j;
            if (kxl >= width) continue;
            int kx = kxg0 + kxl;
            float tbr = tr * Br[j] - ti * Bi[j];
            float tbi = tr * Bi[j] + ti * Br[j];
            d_F[img][kx][u]       = make_float2(Ar[j] + tbr, Ai[j] + tbi);
            d_F[img][kx][u + 100] = make_float2(Ar[j] - tbr, Ai[j] - tbi);
        }
    }
}

// ---------------- combine spectra + inverse ky (radix-2 output split) -------
// For r>=180: lig spectrum synthesized as ph(kx+ky)*conj(F[r-180]),
// ph(s) = e^{-i pi 99 s/100} = (-1)^s (cos(pi s/100) + i sin(pi s/100)).
// ph depends only on s in [0,300] -> shared table, built once per block.
__global__ void __launch_bounds__(320) k_combine_invy(const float* __restrict__ wb,
        const float* __restrict__ wc1, const float* __restrict__ wc2,
        const float* __restrict__ wk) {
    __shared__ __align__(16) float2 sfs[SS][24];
    __shared__ float2 ph[304];
    int chunk = blockIdx.x % 5;
    int imgH = blockIdx.x / 5;
    int b = imgH / RR;
    int r = imgH % RR;
    bool flip = (r >= RRH);
    int rb180 = flip ? r - RRH : r;
    int kxg0 = chunk * 24;
    int width = (KXN - kxg0 < 24) ? (KXN - kxg0) : 24;
    int tid = threadIdx.x;
    float w0 = *wb, w1v = *wc1, w2v = *wc2, w3 = *wk;
    int imgL0 = (b * RRH + rb180) * 2, imgL1 = imgL0 + 1;
    int imgR0 = NLIGH + b * 2, imgR1 = imgR0 + 1;
    if (flip) {
        for (int s = tid; s < 301; s += 320) {
            float pr, pi_;
            sincosf(3.14159265358979f * 0.01f * (float)s, &pi_, &pr);
            if (s & 1) { pr = -pr; pi_ = -pi_; }
            ph[s] = make_float2(pr, pi_);
        }
        __syncthreads();
    }
    for (int e = tid; e < SS * 24; e += 320) {
        int ky = e % SS, kxl = e / SS;
        float2 v = make_float2(0.f, 0.f);
        if (kxl < width) {
            int kx = kxg0 + kxl;
            float2 lb = d_F[imgL0][kx][ky];
            float2 lB = d_F[imgL1][kx][ky];
            if (flip) {
                float2 p = ph[kx + ky];
                float t;
                t    = p.x * lb.x + p.y * lb.y;      // Re(ph*conj(lb))
                lb.y = p.y * lb.x - p.x * lb.y;      // Im(ph*conj(lb))
                lb.x = t;
                t    = p.x * lB.x + p.y * lB.y;
                lB.y = p.y * lB.x - p.x * lB.y;
                lB.x = t;
            }
            float2 rb = d_F[imgR0][kx][ky];
            float2 rB = d_F[imgR1][kx][ky];
            float ur = w0 * lb.x + w1v * lB.x, ui = w0 * lb.y + w1v * lB.y;
            float vr = w2v * lb.x - w3 * lB.x, vi = w2v * lb.y - w3 * lB.y;
            v.x = rb.x * ur + rb.y * ui + rB.x * vr + rB.y * vi;
            v.y = rb.x * ui - rb.y * ur + rB.x * vi - rB.y * vr;
        }
        sfs[ky][kxl] = v;
    }
    __syncthreads();
    for (int task = tid; task < 300; task += 320) {
        int u = task % 100;
        int kxl0 = (task / 100) * 8;
        int uw = (u > 50) ? u - 100 : u;
        float sif, srf;
        sincosf(6.28318530717959f * (float)uw * 0.01f, &sif, &srf);
        float wr = 1.f, wi = 0.f;
        float Pr[8], Pi[8], Qr[8], Qi[8];
#pragma unroll
        for (int j = 0; j < 8; j++) { Pr[j]=Pi[j]=Qr[j]=Qi[j]=0.f; }
        for (int m = 0; m < 100; m++) {
            if ((m & 24) && (m % 25 == 0)) {       // m = 25,50,75
                int j = (2 * u * (m / 25)) & 7;
                wr = C8[j]; wi = S8[j];
            }
            const float4* pe = reinterpret_cast<const float4*>(&sfs[2*m][kxl0]);
            const float4* po = reinterpret_cast<const float4*>(&sfs[2*m+1][kxl0]);
#pragma unroll
            for (int q = 0; q < 4; q++) {
                float4 e = pe[q];
                Pr[2*q]   = fmaf(e.x, wr, Pr[2*q]);   Pr[2*q]   = fmaf(-e.y, wi, Pr[2*q]);
                Pi[2*q]   = fmaf(e.x, wi, Pi[2*q]);   Pi[2*q]   = fmaf( e.y, wr, Pi[2*q]);
                Pr[2*q+1] = fmaf(e.z, wr, Pr[2*q+1]); Pr[2*q+1] = fmaf(-e.w, wi, Pr[2*q+1]);
                Pi[2*q+1] = fmaf(e.z, wi, Pi[2*q+1]); Pi[2*q+1] = fmaf( e.w, wr, Pi[2*q+1]);
                float4 o = po[q];
                Qr[2*q]   = fmaf(o.x, wr, Qr[2*q]);   Qr[2*q]   = fmaf(-o.y, wi, Qr[2*q]);
                Qi[2*q]   = fmaf(o.x, wi, Qi[2*q]);   Qi[2*q]   = fmaf( o.y, wr, Qi[2*q]);
                Qr[2*q+1] = fmaf(o.z, wr, Qr[2*q+1]); Qr[2*q+1] = fmaf(-o.w, wi, Qr[2*q+1]);
                Qi[2*q+1] = fmaf(o.z, wi, Qi[2*q+1]); Qi[2*q+1] = fmaf( o.w, wr, Qi[2*q+1]);
            }
            float nr = fmaf(wr, srf, -wi * sif);
            float ni = fmaf(wr, sif, wi * srf);
            wr = nr; wi = ni;
        }
        float tr, ti;
        sincosf(3.14159265358979f * (float)u * 0.01f, &ti, &tr);
#pragma unroll
        for (int j = 0; j < 8; j++) {
            int kxl = kxl0 + j;
            if (kxl >= width) continue;
            int kx = kxg0 + kxl;
            float tqr = tr * Qr[j] - ti * Qi[j];
            float tqi = tr * Qi[j] + ti * Qr[j];
            d_H[imgH][kx][u]       = make_float2(Pr[j] + tqr, Pi[j] + tqi);
            d_H[imgH][kx][u + 100] = make_float2(Pr[j] - tqr, Pi[j] - tqi);
        }
    }
}

// ---------------- inverse kx (real, radix-2 output split) + reduce ----------
__global__ void __launch_bounds__(256) k_invx_reduce(const int* __restrict__ gtr,
                                                     const int* __restrict__ gtt) {
    __shared__ __align__(16) float2 HT[KXN][20];
    __shared__ float red[256];
    int yc = blockIdx.x % 10;
    int imgH = blockIdx.x / 10;
    int b = imgH / RR, r = imgH % RR;
    int ybase = yc * 20;
    int tid = threadIdx.x;
    for (int e = tid; e < KXN * 20; e += 256) {
        int kx = e / 20, yl = e % 20;
        HT[kx][yl] = d_H[imgH][kx][ybase + yl];
    }
    __syncthreads();
    int gr = gtr[b], t0 = gtt[2 * b], t1 = gtt[2 * b + 1];
    const float inv = 1.0f / 40000.0f;
    float lmax = -3.4e38f;
    for (int task = tid; task < 200; task += 256) {
        int u = task % 100;
        int y0 = (task / 100) * 10;
        int uw = (u > 50) ? u - 100 : u;
        float sif, srf;
        sincosf(6.28318530717959f * (float)uw * 0.01f, &sif, &srf);
        float wr = 1.f, wi = 0.f;
        float E[10], Cr[10], Ci[10];
        float sgn = (u & 1) ? -1.f : 1.f;
#pragma unroll
        for (int i = 0; i < 10; i++) {
            E[i]  = HT[0][y0 + i].x + sgn * HT[100][y0 + i].x;
            Cr[i] = HT[1][y0 + i].x;
            Ci[i] = HT[1][y0 + i].y;
        }
        for (int m = 1; m < 50; m++) {
            float nr = fmaf(wr, srf, -wi * sif);
            float ni = fmaf(wr, sif, wi * srf);
            wr = nr; wi = ni;
            if (m == 25) {
                int j = (2 * u) & 7;
                wr = C8[j]; wi = S8[j];
            }
            float w2r = 2.f * wr, w2i = 2.f * wi;
            const float4* pe = reinterpret_cast<const float4*>(&HT[2*m][y0]);
            const float4* po = reinterpret_cast<const float4*>(&HT[2*m+1][y0]);
#pragma unroll
            for (int q = 0; q < 5; q++) {
                float4 e = pe[q];
                E[2*q]   = fmaf(e.x, w2r, E[2*q]);   E[2*q]   = fmaf(-e.y, w2i, E[2*q]);
                E[2*q+1] = fmaf(e.z, w2r, E[2*q+1]); E[2*q+1] = fmaf(-e.w, w2i, E[2*q+1]);
                float4 o = po[q];
                Cr[2*q]   = fmaf(o.x, wr, Cr[2*q]);   Cr[2*q]   = fmaf(-o.y, wi, Cr[2*q]);
                Ci[2*q]   = fmaf(o.x, wi, Ci[2*q]);   Ci[2*q]   = fmaf( o.y, wr, Ci[2*q]);
                Cr[2*q+1] = fmaf(o.z, wr, Cr[2*q+1]); Cr[2*q+1] = fmaf(-o.w, wi, Cr[2*q+1]);
                Ci[2*q+1] = fmaf(o.z, wi, Ci[2*q+1]); Ci[2*q+1] = fmaf( o.w, wr, Ci[2*q+1]);
            }
        }
        float tr, ti;
        sincosf(3.14159265358979f * (float)u * 0.01f, &ti, &tr);
#pragma unroll
        for (int i = 0; i < 10; i++) {
            float oc = 2.f * (Cr[i] * tr - Ci[i] * ti);
            float s0 = (E[i] + oc) * inv;
            float s1 = (E[i] - oc) * inv;
            lmax = fmaxf(lmax, fmaxf(s0, s1));
            int y = ybase + y0 + i;
            if (r == gr && y == t0) {
                if (u == t1) d_pos[b] = s0;
                if (u + 100 == t1) d_pos[b] = s1;
            }
        }
    }
    red[tid] = lmax;
    __syncthreads();
    for (int s2 = 128; s2 > 0; s2 >>= 1) {
        if (tid < s2) red[tid] = fmaxf(red[tid], red[tid + s2]);
        __syncthreads();
    }
    if (tid == 0) atomicMax(&d_best[b], fenc(red[0]));
}

__global__ void k_final(float* __restrict__ out) {
    if (threadIdx.x == 0) {
        float lp = 0.f, ln = 0.f;
        for (int b = 0; b < NB; b++) {
            float p = d_pos[b];
            lp += p + p * p;
            float m = fdec(d_best[b]);
            ln += -m + m * m;
        }
        out[0] = lp / (float)NB;
        out[1] = ln / (float)NB;
    }
}

extern "C" void kernel_launch(void* const* d_in, const int* in_sizes, int n_in,
                              void* d_out, int out_size) {
    const float* rec = (const float*)d_in[0];
    const float* lig = (const float*)d_in[1];
    const float* w1 = (const float*)d_in[2];
    const float* w2 = (const float*)d_in[3];
    const float* wb = (const float*)d_in[4];
    const float* wc1 = (const float*)d_in[5];
    const float* wc2 = (const float*)d_in[6];
    const float* wk = (const float*)d_in[7];
    const int* gtr = (const int*)d_in[8];
    const int* gtt = (const int*)d_in[9];
    float* out = (float*)d_out;

    k_init<<<1, 32>>>();
    dim3 gconv((NPIX + 255) / 256, 4);
    k_conv1<<<gconv, 256>>>(rec, lig, w1);
    k_conv2<<<gconv, 256>>>(w2);
    k_rot_rowdft<<<NIMGH, 256>>>();
    k_coldft<<<NIMGH * 2, 256>>>();
    k_combine_invy<<<NB * RR * 5, 320>>>(wb, wc1, wc2, wk);
    k_invx_reduce<<<NB * RR * 10, 256>>>(gtr, gtt);
    k_final<<<1, 32>>>(out);
}

// round 10
// speedup vs baseline: 1.9268x; 1.1727x over previous
#include <cuda_runtime.h>
#include <math.h>

#define NB 2
#define RR 360
#define RRH 180
#define NN 100
#define SS 200
#define KXN 101
#define NPIX (NN*NN)
#define NLIGH (NB*RRH*2)          // 720 forward-transformed ligand images
#define NIMGH (NLIGH + NB*2)      // +4 receptor images = 724
#define GPITCH 102

// ---------------- scratch (device globals; no allocation allowed) ----------
__device__ float  d_h1[4][9][NPIX];
__device__ float  d_feat[4][2][NPIX];            // 0..1 receptor b, 2..3 ligand b
__device__ float2 d_G[NIMGH][NN][GPITCH];        // row DFT: [img][y][kx]
__device__ float2 d_F[NIMGH][KXN][SS];           // fwd spectrum: [img][kx][ky]
__device__ float2 d_H[NB*RR][KXN][SS];           // after inv-ky: [imgH][kx][y]
__device__ unsigned int d_best[NB];
__device__ float  d_pos[NB];

// e^{i pi j/4}: cos, sin tables (exact-to-eps reseed points)
__device__ __constant__ float C8[8] = {1.f, 0.70710678118654752f, 0.f, -0.70710678118654752f,
                                       -1.f, -0.70710678118654752f, 0.f, 0.70710678118654752f};
__device__ __constant__ float S8[8] = {0.f, 0.70710678118654752f, 1.f, 0.70710678118654752f,
                                       0.f, -0.70710678118654752f, -1.f, -0.70710678118654752f};

__device__ __forceinline__ unsigned fenc(float f) {
    unsigned u = __float_as_uint(f);
    return (u & 0x80000000u) ? ~u : (u | 0x80000000u);
}
__device__ __forceinline__ float fdec(unsigned e) {
    unsigned u = (e & 0x80000000u) ? (e & 0x7FFFFFFFu) : ~e;
    return __uint_as_float(u);
}

__global__ void k_init() {
    int t = threadIdx.x;
    if (t < NB) { d_best[t] = 0u; d_pos[t] = 0.0f; }
}

// ---------------- conv1 + norm_relu (FIELDS1) -------------------------------
__global__ void k_conv1(const float* __restrict__ rec, const float* __restrict__ lig,
                        const float* __restrict__ w1) {
    int img = blockIdx.y;
    int p = blockIdx.x * blockDim.x + threadIdx.x;
    if (p >= NPIX) return;
    int y = p / NN, x = p % NN;
    const float* src = (img < NB) ? (rec + img * NPIX) : (lig + (img - NB) * NPIX);
    float acc[9];
#pragma unroll
    for (int o = 0; o < 9; o++) acc[o] = 0.0f;
#pragma unroll
    for (int ky = 0; ky < 5; ky++) {
        int iy = y + ky - 2;
        if ((unsigned)iy >= NN) continue;
#pragma unroll
        for (int kx = 0; kx < 5; kx++) {
            int ix = x + kx - 2;
            if ((unsigned)ix >= NN) continue;
            float v = __ldg(src + iy * NN + ix);
#pragma unroll
            for (int o = 0; o < 9; o++)
                acc[o] = fmaf(v, __ldg(w1 + o * 25 + ky * 5 + kx), acc[o]);
        }
    }
    {
        float a = acc[0];
        float n = sqrtf(a * a + 1e-12f);
        d_h1[img][0][p] = a * (n / (n + 1e-12f));
    }
#pragma unroll
    for (int g = 0; g < 4; g++) {
        int s = 1 + 2 * g;
        float a = acc[s], b = acc[s + 1];
        float n = sqrtf(a * a + b * b + 1e-12f);
        float sc = n / (n + 1e-12f);
        d_h1[img][s][p] = a * sc;
        d_h1[img][s + 1][p] = b * sc;
    }
}

// ---------------- conv2 + norm_relu (FIELDS2) + features --------------------
__global__ void k_conv2(const float* __restrict__ w2) {
    int img = blockIdx.y;
    int p = blockIdx.x * blockDim.x + threadIdx.x;
    if (p >= NPIX) return;
    int y = p / NN, x = p % NN;
    float acc[3] = {0.f, 0.f, 0.f};
    for (int ci = 0; ci < 9; ci++) {
        const float* hp = d_h1[img][ci];
#pragma unroll
        for (int ky = 0; ky < 5; ky++) {
            int iy = y + ky - 2;
            if ((unsigned)iy >= NN) continue;
#pragma unroll
            for (int kx = 0; kx < 5; kx++) {
                int ix = x + kx - 2;
                if ((unsigned)ix >= NN) continue;
                float v = hp[iy * NN + ix];
#pragma unroll
                for (int o = 0; o < 3; o++)
                    acc[o] = fmaf(v, __ldg(w2 + ((o * 9 + ci) * 5 + ky) * 5 + kx), acc[o]);
            }
        }
    }
    float o0, o1, o2;
    {
        float a = acc[0];
        float n = sqrtf(a * a + 1e-12f);
        o0 = a * (n / (n + 1e-12f));
    }
    {
        float a = acc[1], b = acc[2];
        float n = sqrtf(a * a + b * b + 1e-12f);
        float sc = n / (n + 1e-12f);
        o1 = a * sc; o2 = b * sc;
    }
    d_feat[img][0][p] = fabsf(o0);
    d_feat[img][1][p] = sqrtf(o1 * o1 + o2 * o2 + 1e-12f);
}

__device__ __forceinline__ float samp(const float* __restrict__ im, float yf, float xf) {
    if (yf < 0.f || yf >= 100.f || xf < 0.f || xf >= 100.f) return 0.f;
    int yc = (int)yf, xc = (int)xf;
    return im[yc * NN + xc];
}

// ---------------- rotate (fused) + row DFT ----------------------------------
// Only rotations r = 0..179 computed; r+180 derived later via phase*conj.
__global__ void __launch_bounds__(256) k_rot_rowdft() {
    __shared__ __align__(16) float rotT[NN * 104];   // [x][y], pitch 104
    int bid = blockIdx.x;
    int tid = threadIdx.x;
    const float* src;
    bool ident;
    float ct = 1.f, st = 0.f;
    if (bid < NLIGH) {
        int c = bid & 1;
        int r = (bid >> 1) % RRH;
        int b = bid / (2 * RRH);
        src = d_feat[NB + b][c];
        double th = -3.14159265358979323846 + (double)r * (6.283185307179586477 / 360.0);
        ct = (float)cos(th); st = (float)sin(th);
        ident = false;
    } else {
        int i = bid - NLIGH;
        src = d_feat[i >> 1][i & 1];
        ident = true;
    }
    for (int p = tid; p < NPIX; p += blockDim.x) {
        int i = p / NN, j = p % NN;
        float val;
        if (ident) {
            val = src[p];
        } else {
            float xs = (float)j - 49.5f, ys = (float)i - 49.5f;
            float xq = ct * xs + st * ys + 49.5f;
            float yq = -st * xs + ct * ys + 49.5f;
            float x0f = floorf(xq), y0f = floorf(yq);
            float wx = xq - x0f, wy = yq - y0f;
            val = samp(src, y0f, x0f) * (1.f - wy) * (1.f - wx)
                + samp(src, y0f, x0f + 1.f) * (1.f - wy) * wx
                + samp(src, y0f + 1.f, x0f) * wy * (1.f - wx)
                + samp(src, y0f + 1.f, x0f + 1.f) * wy * wx;
        }
        rotT[j * 104 + i] = val;   // transposed store
    }
    __syncthreads();
    for (int task = tid; task < 5 * KXN; task += 256) {
        int kx = task % KXN;
        int y0 = (task / KXN) * 20;
        float sif, srf;
        sincosf(-3.14159265358979f * (float)kx * 0.01f, &sif, &srf);  // step e^{-i pi kx/100}
        float wr = 1.f, wi = 0.f;
        float aR[20], aI[20];
#pragma unroll
        for (int i = 0; i < 20; i++) { aR[i] = 0.f; aI[i] = 0.f; }
        for (int x = 0; x < NN; x++) {
            if ((x & 24) && (x % 25 == 0)) {      // x = 25, 50, 75: exact reseed
                int j = (kx * (x / 25)) & 7;      // phase = -pi*j/4
                wr = C8[j]; wi = -S8[j];
            }
            const float4* rp = reinterpret_cast<const float4*>(&rotT[x * 104 + y0]);
#pragma unroll
            for (int q = 0; q < 5; q++) {
                float4 v = rp[q];
                aR[q*4+0] = fmaf(v.x, wr, aR[q*4+0]); aI[q*4+0] = fmaf(v.x, wi, aI[q*4+0]);
                aR[q*4+1] = fmaf(v.y, wr, aR[q*4+1]); aI[q*4+1] = fmaf(v.y, wi, aI[q*4+1]);
                aR[q*4+2] = fmaf(v.z, wr, aR[q*4+2]); aI[q*4+2] = fmaf(v.z, wi, aI[q*4+2]);
                aR[q*4+3] = fmaf(v.w, wr, aR[q*4+3]); aI[q*4+3] = fmaf(v.w, wi, aI[q*4+3]);
            }
            float nr = fmaf(wr, srf, -wi * sif);
            float ni = fmaf(wr, sif, wi * srf);
            wr = nr; wi = ni;
        }
#pragma unroll
        for (int i = 0; i < 20; i++)
            d_G[bid][y0 + i][kx] = make_float2(aR[i], aI[i]);
    }
}

// ---------------- column DFT with radix-2 input split -----------------------
__global__ void __launch_bounds__(256) k_coldft() {
    __shared__ __align__(16) float2 GT[NN][56];   // [y][kx-local]
    int img = blockIdx.x >> 1;
    int half = blockIdx.x & 1;
    int kxg0 = half * 52;
    int width = half ? 49 : 52;
    int tid = threadIdx.x;
    for (int t = tid; t < NN * 56; t += 256) {
        int y = t / 56, kxl = t % 56;
        GT[y][kxl] = (kxl < width) ? d_G[img][y][kxg0 + kxl] : make_float2(0.f, 0.f);
    }
    __syncthreads();
    for (int task = tid; task < 700; task += 256) {
        int u = task % 100;
        int kxl0 = (task / 100) * 8;
        int uw = (u > 50) ? u - 100 : u;
        float sif, srf;
        sincosf(-6.28318530717959f * (float)uw * 0.01f, &sif, &srf);
        float wr = 1.f, wi = 0.f;
        float Ar[8], Ai[8], Br[8], Bi[8];
#pragma unroll
        for (int j = 0; j < 8; j++) { Ar[j]=Ai[j]=Br[j]=Bi[j]=0.f; }
        for (int v = 0; v < 50; v++) {
            if (v == 25) {                         // phase = -pi*u/2 exact
                int j = (2 * u) & 7;
                wr = C8[j]; wi = -S8[j];
            }
            const float4* pe = reinterpret_cast<const float4*>(&GT[2*v][kxl0]);
            const float4* po = reinterpret_cast<const float4*>(&GT[2*v+1][kxl0]);
#pragma unroll
            for (int q = 0; q < 4; q++) {
                float4 e = pe[q];
                Ar[2*q]   = fmaf(e.x, wr, Ar[2*q]);   Ar[2*q]   = fmaf(-e.y, wi, Ar[2*q]);
                Ai[2*q]   = fmaf(e.x, wi, Ai[2*q]);   Ai[2*q]   = fmaf( e.y, wr, Ai[2*q]);
                Ar[2*q+1] = fmaf(e.z, wr, Ar[2*q+1]); Ar[2*q+1] = fmaf(-e.w, wi, Ar[2*q+1]);
                Ai[2*q+1] = fmaf(e.z, wi, Ai[2*q+1]); Ai[2*q+1] = fmaf( e.w, wr, Ai[2*q+1]);
                float4 o = po[q];
                Br[2*q]   = fmaf(o.x, wr, Br[2*q]);   Br[2*q]   = fmaf(-o.y, wi, Br[2*q]);
                Bi[2*q]   = fmaf(o.x, wi, Bi[2*q]);   Bi[2*q]   = fmaf( o.y, wr, Bi[2*q]);
                Br[2*q+1] = fmaf(o.z, wr, Br[2*q+1]); Br[2*q+1] = fmaf(-o.w, wi, Br[2*q+1]);
                Bi[2*q+1] = fmaf(o.z, wi, Bi[2*q+1]); Bi[2*q+1] = fmaf( o.w, wr, Bi[2*q+1]);
            }
            float nr = fmaf(wr, srf, -wi * sif);
            float ni = fmaf(wr, sif, wi * srf);
            wr = nr; wi = ni;
        }
        float tr, ti;
        sincosf(-3.14159265358979f * (float)u * 0.01f, &ti, &tr);
#pragma unroll
        for (int j = 0; j < 8; j++) {
            int kxl = kxl0 + j;
            if (kxl >= width) continue;
            int kx = kxg0 + kxl;
            float tbr = tr * Br[j] - ti * Bi[j];
            float tbi = tr * Bi[j] + ti * Br[j];
            d_F[img][kx][u]       = make_float2(Ar[j] + tbr, Ai[j] + tbi);
            d_F[img][kx][u + 100] = make_float2(Ar[j] - tbr, Ai[j] - tbi);
        }
    }
}

// ---------------- combine spectra + inverse ky (RADIX-4 output split) -------
// ky = 4t+s. S_s(v) = sum_t sf[4t+s] e^{2pi i t v/50}, v=0..49 (shared twiddle).
// H[v+50j] = sum_s i^{s j} t_v^s S_s,  t_v = e^{i pi v/100}.
// For r>=180: lig spectrum synthesized as ph(kx+ky)*conj(F[r-180]) via table.
#define CACC(Sr, Si, f4) \
    Sr[2*q]   = fmaf((f4).x, wr, Sr[2*q]);   Sr[2*q]   = fmaf(-(f4).y, wi, Sr[2*q]); \
    Si[2*q]   = fmaf((f4).x, wi, Si[2*q]);   Si[2*q]   = fmaf( (f4).y, wr, Si[2*q]); \
    Sr[2*q+1] = fmaf((f4).z, wr, Sr[2*q+1]); Sr[2*q+1] = fmaf(-(f4).w, wi, Sr[2*q+1]); \
    Si[2*q+1] = fmaf((f4).z, wi, Si[2*q+1]); Si[2*q+1] = fmaf( (f4).w, wr, Si[2*q+1]);

__global__ void __launch_bounds__(320) k_combine_invy(const float* __restrict__ wb,
        const float* __restrict__ wc1, const float* __restrict__ wc2,
        const float* __restrict__ wk) {
    __shared__ __align__(16) float2 sfs[SS][24];
    __shared__ float2 ph[304];
    int chunk = blockIdx.x % 5;
    int imgH = blockIdx.x / 5;
    int b = imgH / RR;
    int r = imgH % RR;
    bool flip = (r >= RRH);
    int rb180 = flip ? r - RRH : r;
    int kxg0 = chunk * 24;
    int width = (KXN - kxg0 < 24) ? (KXN - kxg0) : 24;
    int tid = threadIdx.x;
    float w0 = *wb, w1v = *wc1, w2v = *wc2, w3 = *wk;
    int imgL0 = (b * RRH + rb180) * 2, imgL1 = imgL0 + 1;
    int imgR0 = NLIGH + b * 2, imgR1 = imgR0 + 1;
    if (flip) {
        for (int s = tid; s < 301; s += 320) {
            float pr, pi_;
            sincosf(3.14159265358979f * 0.01f * (float)s, &pi_, &pr);
            if (s & 1) { pr = -pr; pi_ = -pi_; }
            ph[s] = make_float2(pr, pi_);
        }
        __syncthreads();
    }
    for (int e = tid; e < SS * 24; e += 320) {
        int ky = e % SS, kxl = e / SS;
        float2 v = make_float2(0.f, 0.f);
        if (kxl < width) {
            int kx = kxg0 + kxl;
            float2 lb = d_F[imgL0][kx][ky];
            float2 lB = d_F[imgL1][kx][ky];
            if (flip) {
                float2 p = ph[kx + ky];
                float t;
                t    = p.x * lb.x + p.y * lb.y;      // Re(ph*conj(lb))
                lb.y = p.y * lb.x - p.x * lb.y;      // Im(ph*conj(lb))
                lb.x = t;
                t    = p.x * lB.x + p.y * lB.y;
                lB.y = p.y * lB.x - p.x * lB.y;
                lB.x = t;
            }
            float2 rb = d_F[imgR0][kx][ky];
            float2 rB = d_F[imgR1][kx][ky];
            float ur = w0 * lb.x + w1v * lB.x, ui = w0 * lb.y + w1v * lB.y;
            float vr = w2v * lb.x - w3 * lB.x, vi = w2v * lb.y - w3 * lB.y;
            v.x = rb.x * ur + rb.y * ui + rB.x * vr + rB.y * vi;
            v.y = rb.x * ui - rb.y * ur + rB.x * vi - rB.y * vr;
        }
        sfs[ky][kxl] = v;
    }
    __syncthreads();
    // 300 tasks = 6 kx-groups of 4 x 50 v-values (v fastest)
    for (int task = tid; task < 300; task += 320) {
        int v = task % 50;
        int kxl0 = (task / 50) * 4;
        int vw = (v > 25) ? v - 50 : v;
        float sif, srf;
        sincosf(6.28318530717959f * (float)vw * 0.02f, &sif, &srf);  // step e^{2pi i v/50}
        float wr = 1.f, wi = 0.f;
        float S0r[4], S0i[4], S1r[4], S1i[4], S2r[4], S2i[4], S3r[4], S3i[4];
#pragma unroll
        for (int j = 0; j < 4; j++) { S0r[j]=S0i[j]=S1r[j]=S1i[j]=S2r[j]=S2i[j]=S3r[j]=S3i[j]=0.f; }
        for (int t = 0; t < 50; t++) {
            if (t == 25) {                          // phase = pi*v exact
                wr = (v & 1) ? -1.f : 1.f; wi = 0.f;
            }
            const float4* p0 = reinterpret_cast<const float4*>(&sfs[4*t    ][kxl0]);
            const float4* p1 = reinterpret_cast<const float4*>(&sfs[4*t + 1][kxl0]);
            const float4* p2 = reinterpret_cast<const float4*>(&sfs[4*t + 2][kxl0]);
            const float4* p3 = reinterpret_cast<const float4*>(&sfs[4*t + 3][kxl0]);
#pragma unroll
            for (int q = 0; q < 2; q++) {
                float4 e0 = p0[q]; CACC(S0r, S0i, e0)
                float4 e1 = p1[q]; CACC(S1r, S1i, e1)
                float4 e2 = p2[q]; CACC(S2r, S2i, e2)
                float4 e3 = p3[q]; CACC(S3r, S3i, e3)
            }
            float nr = fmaf(wr, srf, -wi * sif);
            float ni = fmaf(wr, sif, wi * srf);
            wr = nr; wi = ni;
        }
        float tr, ti;
        sincosf(3.14159265358979f * 0.01f * (float)v, &ti, &tr);   // t_v = e^{i pi v/100}
        float t2r = tr * tr - ti * ti, t2i = 2.f * tr * ti;
        float t3r = t2r * tr - t2i * ti, t3i = t2r * ti + t2i * tr;
#pragma unroll
        for (int j = 0; j < 4; j++) {
            int kxl = kxl0 + j;
            if (kxl >= width) continue;
            int kx = kxg0 + kxl;
            float ar = S0r[j], ai = S0i[j];
            float br = tr * S1r[j] - ti * S1i[j],   bi = tr * S1i[j] + ti * S1r[j];
            float cr = t2r * S2r[j] - t2i * S2i[j], ci = t2r * S2i[j] + t2i * S2r[j];
            float dr = t3r * S3r[j] - t3i * S3i[j], di = t3r * S3i[j] + t3i * S3r[j];
            float acr = ar + cr, aci = ai + ci;
            float amr = ar - cr, ami = ai - ci;
            float bdr = br + dr, bdi = bi + di;
            float bmr = br - dr, bmi = bi - di;
            d_H[imgH][kx][v]       = make_float2(acr + bdr, aci + bdi);
            d_H[imgH][kx][v + 100] = make_float2(acr - bdr, aci - bdi);
            d_H[imgH][kx][v + 50]  = make_float2(amr - bmi, ami + bmr);   // +i(b-d)
            d_H[imgH][kx][v + 150] = make_float2(amr + bmi, ami - bmr);   // -i(b-d)
        }
    }
}

// ---------------- inverse kx (real, radix-2 output split) + reduce ----------
__global__ void __launch_bounds__(256) k_invx_reduce(const int* __restrict__ gtr,
                                                     const int* __restrict__ gtt) {
    __shared__ __align__(16) float2 HT[KXN][20];
    __shared__ float red[256];
    int yc = blockIdx.x % 10;
    int imgH = blockIdx.x / 10;
    int b = imgH / RR, r = imgH % RR;
    int ybase = yc * 20;
    int tid = threadIdx.x;
    for (int e = tid; e < KXN * 20; e += 256) {
        int kx = e / 20, yl = e % 20;
        HT[kx][yl] = d_H[imgH][kx][ybase + yl];
    }
    __syncthreads();
    int gr = gtr[b], t0 = gtt[2 * b], t1 = gtt[2 * b + 1];
    const float inv = 1.0f / 40000.0f;
    float lmax = -3.4e38f;
    for (int task = tid; task < 200; task += 256) {
        int u = task % 100;
        int y0 = (task / 100) * 10;
        int uw = (u > 50) ? u - 100 : u;
        float sif, srf;
        sincosf(6.28318530717959f * (float)uw * 0.01f, &sif, &srf);
        float wr = 1.f, wi = 0.f;
        float E[10], Cr[10], Ci[10];
        float sgn = (u & 1) ? -1.f : 1.f;
#pragma unroll
        for (int i = 0; i < 10; i++) {
            E[i]  = HT[0][y0 + i].x + sgn * HT[100][y0 + i].x;
            Cr[i] = HT[1][y0 + i].x;
            Ci[i] = HT[1][y0 + i].y;
        }
        for (int m = 1; m < 50; m++) {
            float nr = fmaf(wr, srf, -wi * sif);
            float ni = fmaf(wr, sif, wi * srf);
            wr = nr; wi = ni;
            if (m == 25) {
                int j = (2 * u) & 7;
                wr = C8[j]; wi = S8[j];
            }
            float w2r = 2.f * wr, w2i = 2.f * wi;
            const float4* pe = reinterpret_cast<const float4*>(&HT[2*m][y0]);
            const float4* po = reinterpret_cast<const float4*>(&HT[2*m+1][y0]);
#pragma unroll
            for (int q = 0; q < 5; q++) {
                float4 e = pe[q];
                E[2*q]   = fmaf(e.x, w2r, E[2*q]);   E[2*q]   = fmaf(-e.y, w2i, E[2*q]);
                E[2*q+1] = fmaf(e.z, w2r, E[2*q+1]); E[2*q+1] = fmaf(-e.w, w2i, E[2*q+1]);
                float4 o = po[q];
                Cr[2*q]   = fmaf(o.x, wr, Cr[2*q]);   Cr[2*q]   = fmaf(-o.y, wi, Cr[2*q]);
                Ci[2*q]   = fmaf(o.x, wi, Ci[2*q]);   Ci[2*q]   = fmaf( o.y, wr, Ci[2*q]);
                Cr[2*q+1] = fmaf(o.z, wr, Cr[2*q+1]); Cr[2*q+1] = fmaf(-o.w, wi, Cr[2*q+1]);
                Ci[2*q+1] = fmaf(o.z, wi, Ci[2*q+1]); Ci[2*q+1] = fmaf( o.w, wr, Ci[2*q+1]);
            }
        }
        float tr, ti;
        sincosf(3.14159265358979f * (float)u * 0.01f, &ti, &tr);
#pragma unroll
        for (int i = 0; i < 10; i++) {
            float oc = 2.f * (Cr[i] * tr - Ci[i] * ti);
            float s0 = (E[i] + oc) * inv;
            float s1 = (E[i] - oc) * inv;
            lmax = fmaxf(lmax, fmaxf(s0, s1));
            int y = ybase + y0 + i;
            if (r == gr && y == t0) {
                if (u == t1) d_pos[b] = s0;
                if (u + 100 == t1) d_pos[b] = s1;
            }
        }
    }
    red[tid] = lmax;
    __syncthreads();
    for (int s2 = 128; s2 > 0; s2 >>= 1) {
        if (tid < s2) red[tid] = fmaxf(red[tid], red[tid + s2]);
        __syncthreads();
    }
    if (tid == 0) atomicMax(&d_best[b], fenc(red[0]));
}

__global__ void k_final(float* __restrict__ out) {
    if (threadIdx.x == 0) {
        float lp = 0.f, ln = 0.f;
        for (int b = 0; b < NB; b++) {
            float p = d_pos[b];
            lp += p + p * p;
            float m = fdec(d_best[b]);
            ln += -m + m * m;
        }
        out[0] = lp / (float)NB;
        out[1] = ln / (float)NB;
    }
}

extern "C" void kernel_launch(void* const* d_in, const int* in_sizes, int n_in,
                              void* d_out, int out_size) {
    const float* rec = (const float*)d_in[0];
    const float* lig = (const float*)d_in[1];
    const float* w1 = (const float*)d_in[2];
    const float* w2 = (const float*)d_in[3];
    const float* wb = (const float*)d_in[4];
    const float* wc1 = (const float*)d_in[5];
    const float* wc2 = (const float*)d_in[6];
    const float* wk = (const float*)d_in[7];
    const int* gtr = (const int*)d_in[8];
    const int* gtt = (const int*)d_in[9];
    float* out = (float*)d_out;

    k_init<<<1, 32>>>();
    dim3 gconv((NPIX + 255) / 256, 4);
    k_conv1<<<gconv, 256>>>(rec, lig, w1);
    k_conv2<<<gconv, 256>>>(w2);
    k_rot_rowdft<<<NIMGH, 256>>>();
    k_coldft<<<NIMGH * 2, 256>>>();
    k_combine_invy<<<NB * RR * 5, 320>>>(wb, wc1, wc2, wk);
    k_invx_reduce<<<NB * RR * 10, 256>>>(gtr, gtt);
    k_final<<<1, 32>>>(out);
}